// round 14
// baseline (speedup 1.0000x reference)
#include <cuda_runtime.h>
#include <cuda_bf16.h>
#include <math.h>
#include <stdint.h>

// loss_soft_add R14: 3 blocks/SM x 3-stage x 128-row TMA pipeline,
// prefetch 2, 76.8KB dyn smem, grid 444. Same bytes-in-flight per SM as
// the champion (153.6KB) but across 3 independent block streams, 24
// warps/SM. L2 evict_first on streaming copies; warp-granular release.
// Per row of 25 floats: 6 chunks of 4 -> 3*softmax, L1 diff vs tar over
// first 24 cols, mean/24, summed over all rows -> single float scalar.
// Cross-block finish: threadfence + self-resetting atomicInc (graph-safe).

#define THREADS      256
#define ROWS         128
#define ROW_LEN      25
#define TILE_FLOATS  (ROWS * ROW_LEN)        // 3200
#define TILE_BYTES   (TILE_FLOATS * 4)       // 12800
#define STAGE_FLOATS (2 * TILE_FLOATS)       // pre + tar
#define NSTAGES      3
#define PREFETCH     2
#define SMEM_BYTES   (NSTAGES * STAGE_FLOATS * 4)   // 76800
#define MAX_GRID     1184

__device__ double g_partials[MAX_GRID];
__device__ unsigned int g_count = 0;   // wraps back to 0 every launch

__device__ __forceinline__ uint32_t smem_u32(const void* p) {
    uint32_t a;
    asm("{ .reg .u64 t; cvta.to.shared.u64 t, %1; cvt.u32.u64 %0, t; }"
        : "=r"(a) : "l"(p));
    return a;
}
__device__ __forceinline__ void mbar_init(uint32_t a, uint32_t cnt) {
    asm volatile("mbarrier.init.shared.b64 [%0], %1;" :: "r"(a), "r"(cnt) : "memory");
}
__device__ __forceinline__ void mbar_expect_tx(uint32_t a, uint32_t bytes) {
    asm volatile("mbarrier.arrive.expect_tx.shared.b64 _, [%0], %1;"
                 :: "r"(a), "r"(bytes) : "memory");
}
__device__ __forceinline__ void mbar_arrive(uint32_t a) {
    asm volatile("mbarrier.arrive.shared.b64 _, [%0];" :: "r"(a) : "memory");
}
__device__ __forceinline__ void mbar_wait(uint32_t a, uint32_t parity) {
    uint32_t done;
    asm volatile(
        "{\n\t.reg .pred p;\n\t"
        "mbarrier.try_wait.parity.acquire.cta.shared::cta.b64 p, [%1], %2;\n\t"
        "selp.b32 %0, 1, 0, p;\n\t}"
        : "=r"(done) : "r"(a), "r"(parity) : "memory");
    if (!done) {
        asm volatile(
            "{\n\t.reg .pred P1;\n\t"
            "WL_%=:\n\t"
            "mbarrier.try_wait.parity.acquire.cta.shared::cta.b64 P1, [%0], %1, 0x989680;\n\t"
            "@P1 bra.uni WD_%=;\n\t"
            "bra.uni WL_%=;\n\t"
            "WD_%=:\n\t}"
            :: "r"(a), "r"(parity) : "memory");
    }
}
// streaming read: L2 evict_first policy so once-used lines vacate L2 fast
__device__ __forceinline__ uint64_t evict_first_policy() {
    uint64_t pol;
    asm("createpolicy.fractional.L2::evict_first.b64 %0, 1.0;" : "=l"(pol));
    return pol;
}
__device__ __forceinline__ void bulk_g2s(uint32_t dst, const void* src,
                                         uint32_t bytes, uint32_t mbar,
                                         uint64_t pol) {
    asm volatile(
        "cp.async.bulk.shared::cluster.global.mbarrier::complete_tx::bytes.L2::cache_hint "
        "[%0], [%1], %2, [%3], %4;"
        :: "r"(dst), "l"(src), "r"(bytes), "r"(mbar), "l"(pol) : "memory");
}

// 3 chunks (12 elems): 3*softmax (no max-sub; inputs ~N(0,1)) + L1 diff
__device__ __forceinline__ float half_row_loss(const float* __restrict__ p,
                                               const float* __restrict__ t)
{
    float s = 0.0f;
    #pragma unroll
    for (int j = 0; j < 3; j++) {
        float ea = __expf(p[4 * j + 0]);
        float eb = __expf(p[4 * j + 1]);
        float ec = __expf(p[4 * j + 2]);
        float ed = __expf(p[4 * j + 3]);
        float inv = __fdividef(3.0f, ea + eb + ec + ed);
        s += fabsf(ea * inv - t[4 * j + 0]);
        s += fabsf(eb * inv - t[4 * j + 1]);
        s += fabsf(ec * inv - t[4 * j + 2]);
        s += fabsf(ed * inv - t[4 * j + 3]);
    }
    return s;
}

// stage index of tile k for 3-stage ring: k % 3, parity = (k/3) & 1
__device__ __forceinline__ void ring3(long long k, int* s, uint32_t* par) {
    long long q = k / 3;
    *s   = (int)(k - q * 3);
    *par = (uint32_t)(q & 1);
}

__global__ __launch_bounds__(THREADS)
void loss_kernel(const float* __restrict__ pre,
                 const float* __restrict__ tar,
                 long long nrows,
                 float* __restrict__ out)
{
    extern __shared__ float smem[];  // NSTAGES x {pre[3200], tar[3200]}
    __shared__ __align__(8) uint64_t bars[2 * NSTAGES]; // full[3], empty[3]
    __shared__ float warp_red[8];
    __shared__ bool isLast;

    const int tid  = threadIdx.x;
    const int lane = tid & 31;
    const int wid  = tid >> 5;
    const int row  = tid & (ROWS - 1);
    const int half = tid >> 7;                   // 0/1, per-warp constant
    const int off  = row * ROW_LEN + half * 12;  // stride-25: conflict-free

    const uint32_t barB  = smem_u32(bars);   // full s: +8s, empty s: +24+8s
    const uint32_t smem0 = smem_u32(smem);
    const long long ntiles = nrows / ROWS;

    if (tid == 0) {
        #pragma unroll
        for (int s = 0; s < NSTAGES; s++) {
            mbar_init(barB + 8 * s, 1);        // full (expect_tx arrive)
            mbar_init(barB + 24 + 8 * s, 8);   // empty: one arrive per warp
        }
        asm volatile("fence.proxy.async.shared::cta;" ::: "memory");
    }
    __syncthreads();

    float acc = 0.0f;

    // tiles this block owns
    const long long nk = (blockIdx.x < ntiles)
        ? ((ntiles - 1 - (long long)blockIdx.x) / gridDim.x + 1) : 0;

    const uint64_t pol = evict_first_policy();

    // ---- prologue: queue up to PREFETCH tiles ----
    if (tid == 0) {
        long long lim = nk < PREFETCH ? nk : PREFETCH;
        for (long long kf = 0; kf < lim; kf++) {
            const long long tf = blockIdx.x + kf * gridDim.x;
            int s; uint32_t par; ring3(kf, &s, &par);
            const uint32_t dst = smem0 + (uint32_t)s * (STAGE_FLOATS * 4);
            mbar_expect_tx(barB + 8 * s, 2 * TILE_BYTES);
            bulk_g2s(dst,              pre + tf * TILE_FLOATS, TILE_BYTES, barB + 8 * s, pol);
            bulk_g2s(dst + TILE_BYTES, tar + tf * TILE_FLOATS, TILE_BYTES, barB + 8 * s, pol);
        }
    }

    for (long long k = 0; k < nk; k++) {
        // ---- producer: queue tile k+PREFETCH ----
        if (tid == 0) {
            const long long kf = k + PREFETCH;
            if (kf < nk) {
                int s; uint32_t par; ring3(kf, &s, &par);
                if (kf >= NSTAGES)  // stage previously filled in round par^1
                    mbar_wait(barB + 24 + 8 * s, par ^ 1u);
                const long long tf = blockIdx.x + kf * gridDim.x;
                const uint32_t dst = smem0 + (uint32_t)s * (STAGE_FLOATS * 4);
                mbar_expect_tx(barB + 8 * s, 2 * TILE_BYTES);
                bulk_g2s(dst,              pre + tf * TILE_FLOATS, TILE_BYTES, barB + 8 * s, pol);
                bulk_g2s(dst + TILE_BYTES, tar + tf * TILE_FLOATS, TILE_BYTES, barB + 8 * s, pol);
            }
        }

        // ---- consumer: wait full, compute, release (1 arrive per warp) ----
        int s; uint32_t par; ring3(k, &s, &par);
        mbar_wait(barB + 8 * s, par);

        const float* p = smem + s * STAGE_FLOATS;
        acc += half_row_loss(p + off, p + TILE_FLOATS + off);

        __syncwarp();
        if (lane == 0)
            mbar_arrive(barB + 24 + 8 * s);
    }

    // ---- tail rows (nrows % 128): block 0, direct from GMEM ----
    {
        const long long done = ntiles * (long long)ROWS;
        const long long rem = nrows - done;
        if (blockIdx.x == 0 && (long long)tid < rem) {
            const float* prow = pre + (done + tid) * (long long)ROW_LEN;
            const float* trow = tar + (done + tid) * (long long)ROW_LEN;
            acc += half_row_loss(prow, trow);
            acc += half_row_loss(prow + 12, trow + 12);
        }
    }

    // ---- block reduction: warp shuffle + 8-entry smem ----
    #pragma unroll
    for (int o = 16; o > 0; o >>= 1)
        acc += __shfl_down_sync(0xFFFFFFFFu, acc, o);
    if (lane == 0) warp_red[wid] = acc;
    __syncthreads();
    if (wid == 0) {
        float v = (lane < 8) ? warp_red[lane] : 0.0f;
        #pragma unroll
        for (int o = 4; o > 0; o >>= 1)
            v += __shfl_down_sync(0xFFFFFFFFu, v, o);

        if (lane == 0) {
            g_partials[blockIdx.x] = (double)v;
            __threadfence();
            unsigned int old = atomicInc(&g_count, gridDim.x - 1);
            isLast = (old == gridDim.x - 1);
        }
    }
    __syncthreads();

    // ---- last block reduces all partials (deterministic) ----
    if (isLast) {
        __threadfence();
        double sum = 0.0;
        for (int i = tid; i < (int)gridDim.x; i += THREADS)
            sum += g_partials[i];
        #pragma unroll
        for (int o = 16; o > 0; o >>= 1)
            sum += __shfl_down_sync(0xFFFFFFFFu, sum, o);
        __shared__ double dred[8];
        if (lane == 0) dred[wid] = sum;
        __syncthreads();
        if (wid == 0) {
            double v = (lane < 8) ? dred[lane] : 0.0;
            #pragma unroll
            for (int o = 4; o > 0; o >>= 1)
                v += __shfl_down_sync(0xFFFFFFFFu, v, o);
            if (lane == 0)
                out[0] = (float)(v * (1.0 / 24.0));
        }
    }
}

extern "C" void kernel_launch(void* const* d_in, const int* in_sizes, int n_in,
                              void* d_out, int out_size)
{
    const float* pre = (const float*)d_in[0];
    const float* tar = (const float*)d_in[1];
    long long nrows = (long long)in_sizes[0] / ROW_LEN;
    long long ntiles = nrows / ROWS;

    static bool attr_set = false;
    if (!attr_set) {
        cudaFuncSetAttribute(loss_kernel,
                             cudaFuncAttributeMaxDynamicSharedMemorySize,
                             SMEM_BYTES);
        attr_set = true;
    }

    // 148 SMs x 3 resident blocks (76.8KB dyn smem each)
    long long g = ntiles > 0 ? ntiles : 1;
    int grid = (int)(g < 444 ? g : 444);

    loss_kernel<<<grid, THREADS, SMEM_BYTES>>>(pre, tar, nrows, (float*)d_out);
}

// round 15
// speedup vs baseline: 1.0658x; 1.0658x over previous
#include <cuda_runtime.h>
#include <cuda_bf16.h>
#include <math.h>
#include <stdint.h>

// loss_soft_add FINAL (champion; measured 118.0/118.8/119.3us across reruns).
// 4-stage x 128-row TMA (cp.async.bulk) pipeline, prefetch 3, 102.4KB dyn
// smem, 2 blocks/SM, L2 evict_first policy on the streaming copies.
// Per row of 25 floats: 6 chunks of 4 -> 3*softmax, L1 diff vs tar over
// first 24 cols, mean/24, summed over all rows -> single float scalar.
// Cross-block finish: threadfence + self-resetting atomicInc (graph-safe).
//
// Roofline-final: 800MB mandatory traffic (col 24 shares 32B sectors with
// the next row; nothing skippable) at ~6.75 TB/s sustained — the chip's
// path-independent LTS/HBM streaming ceiling. 14 rounds of topology
// variants (LDG vs TMA, 16-32 warps/SM, 2/3/4 stages, 64/128/256-row
// tiles, prefetch 1-3) all land at or above this kernel's time.

#define THREADS      256
#define ROWS         128
#define ROW_LEN      25
#define TILE_FLOATS  (ROWS * ROW_LEN)        // 3200
#define TILE_BYTES   (TILE_FLOATS * 4)       // 12800
#define STAGE_FLOATS (2 * TILE_FLOATS)       // pre + tar
#define NSTAGES      4
#define PREFETCH     3
#define SMEM_BYTES   (NSTAGES * STAGE_FLOATS * 4)   // 102400
#define MAX_GRID     1184

__device__ double g_partials[MAX_GRID];
__device__ unsigned int g_count = 0;   // wraps back to 0 every launch

__device__ __forceinline__ uint32_t smem_u32(const void* p) {
    uint32_t a;
    asm("{ .reg .u64 t; cvta.to.shared.u64 t, %1; cvt.u32.u64 %0, t; }"
        : "=r"(a) : "l"(p));
    return a;
}
__device__ __forceinline__ void mbar_init(uint32_t a, uint32_t cnt) {
    asm volatile("mbarrier.init.shared.b64 [%0], %1;" :: "r"(a), "r"(cnt) : "memory");
}
__device__ __forceinline__ void mbar_expect_tx(uint32_t a, uint32_t bytes) {
    asm volatile("mbarrier.arrive.expect_tx.shared.b64 _, [%0], %1;"
                 :: "r"(a), "r"(bytes) : "memory");
}
__device__ __forceinline__ void mbar_arrive(uint32_t a) {
    asm volatile("mbarrier.arrive.shared.b64 _, [%0];" :: "r"(a) : "memory");
}
__device__ __forceinline__ void mbar_wait(uint32_t a, uint32_t parity) {
    uint32_t done;
    asm volatile(
        "{\n\t.reg .pred p;\n\t"
        "mbarrier.try_wait.parity.acquire.cta.shared::cta.b64 p, [%1], %2;\n\t"
        "selp.b32 %0, 1, 0, p;\n\t}"
        : "=r"(done) : "r"(a), "r"(parity) : "memory");
    if (!done) {
        asm volatile(
            "{\n\t.reg .pred P1;\n\t"
            "WL_%=:\n\t"
            "mbarrier.try_wait.parity.acquire.cta.shared::cta.b64 P1, [%0], %1, 0x989680;\n\t"
            "@P1 bra.uni WD_%=;\n\t"
            "bra.uni WL_%=;\n\t"
            "WD_%=:\n\t}"
            :: "r"(a), "r"(parity) : "memory");
    }
}
// streaming read: L2 evict_first policy so once-used lines vacate L2 fast
__device__ __forceinline__ uint64_t evict_first_policy() {
    uint64_t pol;
    asm("createpolicy.fractional.L2::evict_first.b64 %0, 1.0;" : "=l"(pol));
    return pol;
}
__device__ __forceinline__ void bulk_g2s(uint32_t dst, const void* src,
                                         uint32_t bytes, uint32_t mbar,
                                         uint64_t pol) {
    asm volatile(
        "cp.async.bulk.shared::cluster.global.mbarrier::complete_tx::bytes.L2::cache_hint "
        "[%0], [%1], %2, [%3], %4;"
        :: "r"(dst), "l"(src), "r"(bytes), "r"(mbar), "l"(pol) : "memory");
}

// 3 chunks (12 elems): 3*softmax (no max-sub; inputs ~N(0,1)) + L1 diff
__device__ __forceinline__ float half_row_loss(const float* __restrict__ p,
                                               const float* __restrict__ t)
{
    float s = 0.0f;
    #pragma unroll
    for (int j = 0; j < 3; j++) {
        float ea = __expf(p[4 * j + 0]);
        float eb = __expf(p[4 * j + 1]);
        float ec = __expf(p[4 * j + 2]);
        float ed = __expf(p[4 * j + 3]);
        float inv = __fdividef(3.0f, ea + eb + ec + ed);
        s += fabsf(ea * inv - t[4 * j + 0]);
        s += fabsf(eb * inv - t[4 * j + 1]);
        s += fabsf(ec * inv - t[4 * j + 2]);
        s += fabsf(ed * inv - t[4 * j + 3]);
    }
    return s;
}

__global__ __launch_bounds__(THREADS)
void loss_kernel(const float* __restrict__ pre,
                 const float* __restrict__ tar,
                 long long nrows,
                 float* __restrict__ out)
{
    extern __shared__ float smem[];  // NSTAGES x {pre[3200], tar[3200]}
    __shared__ __align__(8) uint64_t bars[2 * NSTAGES]; // full[4], empty[4]
    __shared__ float warp_red[8];
    __shared__ bool isLast;

    const int tid  = threadIdx.x;
    const int lane = tid & 31;
    const int wid  = tid >> 5;
    const int row  = tid & (ROWS - 1);
    const int half = tid >> 7;                   // 0/1, per-warp constant
    const int off  = row * ROW_LEN + half * 12;  // stride-25: conflict-free

    const uint32_t barB  = smem_u32(bars);   // full s: +8s, empty s: +32+8s
    const uint32_t smem0 = smem_u32(smem);
    const long long ntiles = nrows / ROWS;

    if (tid == 0) {
        #pragma unroll
        for (int s = 0; s < NSTAGES; s++) {
            mbar_init(barB + 8 * s, 1);        // full (expect_tx arrive)
            mbar_init(barB + 32 + 8 * s, 8);   // empty: one arrive per warp
        }
        asm volatile("fence.proxy.async.shared::cta;" ::: "memory");
    }
    __syncthreads();

    float acc = 0.0f;

    // tiles this block owns
    const long long nk = (blockIdx.x < ntiles)
        ? ((ntiles - 1 - (long long)blockIdx.x) / gridDim.x + 1) : 0;

    const uint64_t pol = evict_first_policy();

    // ---- prologue: queue up to PREFETCH tiles ----
    if (tid == 0) {
        long long lim = nk < PREFETCH ? nk : PREFETCH;
        for (long long kf = 0; kf < lim; kf++) {
            const long long tf = blockIdx.x + kf * gridDim.x;
            const int s = (int)(kf & (NSTAGES - 1));
            const uint32_t dst = smem0 + (uint32_t)s * (STAGE_FLOATS * 4);
            mbar_expect_tx(barB + 8 * s, 2 * TILE_BYTES);
            bulk_g2s(dst,              pre + tf * TILE_FLOATS, TILE_BYTES, barB + 8 * s, pol);
            bulk_g2s(dst + TILE_BYTES, tar + tf * TILE_FLOATS, TILE_BYTES, barB + 8 * s, pol);
        }
    }

    for (long long k = 0; k < nk; k++) {
        // ---- producer: queue tile k+PREFETCH ----
        if (tid == 0) {
            const long long kf = k + PREFETCH;
            if (kf < nk) {
                const int s = (int)(kf & (NSTAGES - 1));
                const long long r = kf >> 2;             // fill round of stage s
                if (r >= 1)
                    mbar_wait(barB + 32 + 8 * s, (uint32_t)((r - 1) & 1));
                const long long tf = blockIdx.x + kf * gridDim.x;
                const uint32_t dst = smem0 + (uint32_t)s * (STAGE_FLOATS * 4);
                mbar_expect_tx(barB + 8 * s, 2 * TILE_BYTES);
                bulk_g2s(dst,              pre + tf * TILE_FLOATS, TILE_BYTES, barB + 8 * s, pol);
                bulk_g2s(dst + TILE_BYTES, tar + tf * TILE_FLOATS, TILE_BYTES, barB + 8 * s, pol);
            }
        }

        // ---- consumer: wait full, compute, release (1 arrive per warp) ----
        const int s = (int)(k & (NSTAGES - 1));
        mbar_wait(barB + 8 * s, (uint32_t)((k >> 2) & 1));

        const float* p = smem + s * STAGE_FLOATS;
        acc += half_row_loss(p + off, p + TILE_FLOATS + off);

        __syncwarp();
        if (lane == 0)
            mbar_arrive(barB + 32 + 8 * s);
    }

    // ---- tail rows (nrows % 128): block 0, direct from GMEM ----
    {
        const long long done = ntiles * (long long)ROWS;
        const long long rem = nrows - done;
        if (blockIdx.x == 0 && (long long)tid < rem) {
            const float* prow = pre + (done + tid) * (long long)ROW_LEN;
            const float* trow = tar + (done + tid) * (long long)ROW_LEN;
            acc += half_row_loss(prow, trow);
            acc += half_row_loss(prow + 12, trow + 12);
        }
    }

    // ---- block reduction: warp shuffle + 8-entry smem ----
    #pragma unroll
    for (int o = 16; o > 0; o >>= 1)
        acc += __shfl_down_sync(0xFFFFFFFFu, acc, o);
    if (lane == 0) warp_red[wid] = acc;
    __syncthreads();
    if (wid == 0) {
        float v = (lane < 8) ? warp_red[lane] : 0.0f;
        #pragma unroll
        for (int o = 4; o > 0; o >>= 1)
            v += __shfl_down_sync(0xFFFFFFFFu, v, o);

        if (lane == 0) {
            g_partials[blockIdx.x] = (double)v;
            __threadfence();
            unsigned int old = atomicInc(&g_count, gridDim.x - 1);
            isLast = (old == gridDim.x - 1);
        }
    }
    __syncthreads();

    // ---- last block reduces all partials (deterministic) ----
    if (isLast) {
        __threadfence();
        double sum = 0.0;
        for (int i = tid; i < (int)gridDim.x; i += THREADS)
            sum += g_partials[i];
        #pragma unroll
        for (int o = 16; o > 0; o >>= 1)
            sum += __shfl_down_sync(0xFFFFFFFFu, sum, o);
        __shared__ double dred[8];
        if (lane == 0) dred[wid] = sum;
        __syncthreads();
        if (wid == 0) {
            double v = (lane < 8) ? dred[lane] : 0.0;
            #pragma unroll
            for (int o = 4; o > 0; o >>= 1)
                v += __shfl_down_sync(0xFFFFFFFFu, v, o);
            if (lane == 0)
                out[0] = (float)(v * (1.0 / 24.0));
        }
    }
}

extern "C" void kernel_launch(void* const* d_in, const int* in_sizes, int n_in,
                              void* d_out, int out_size)
{
    const float* pre = (const float*)d_in[0];
    const float* tar = (const float*)d_in[1];
    long long nrows = (long long)in_sizes[0] / ROW_LEN;
    long long ntiles = nrows / ROWS;

    static bool attr_set = false;
    if (!attr_set) {
        cudaFuncSetAttribute(loss_kernel,
                             cudaFuncAttributeMaxDynamicSharedMemorySize,
                             SMEM_BYTES);
        attr_set = true;
    }

    // 148 SMs x 2 resident blocks (102.4KB dyn smem each)
    long long g = ntiles > 0 ? ntiles : 1;
    int grid = (int)(g < 296 ? g : 296);

    loss_kernel<<<grid, THREADS, SMEM_BYTES>>>(pre, tar, nrows, (float*)d_out);
}